// round 1
// baseline (speedup 1.0000x reference)
#include <cuda_runtime.h>

#define NN 3000
#define TT 20
#define IND 6
#define HD 64
#define NH 8
#define NB1 8
#define MAXNZ 1024

// ---------------- scratch (no allocation allowed) ----------------
__device__ float g_WhhT[HD * 192];          // transposed recurrent weights
__device__ float g_support[NN * HD];        // GRU final hidden
__device__ float g_s[2][NN * HD];           // per-graph head features  [n][h*8+f]
__device__ float g_f1[2][NH * NN];          // source scores  [g][h*N+n]
__device__ float g_f2[2][NH * NN];          // dest scores    [g][h*N+n]
__device__ float g_att[2][NN * HD];         // attention outputs
__device__ float g_emb[NN * HD];            // pre-pairnorm embedding
__device__ float g_colsum[HD];              // column sums for pairnorm mean

__device__ __forceinline__ float sigm(float x) { return 1.0f / (1.0f + __expf(-x)); }
__device__ __forceinline__ float tanhfast(float x) { return 2.0f * sigm(2.0f * x) - 1.0f; }

// ---------------- K0: transpose Whh + zero colsum ----------------
__global__ void prep_kernel(const float* __restrict__ Whh) {
    int i = blockIdx.x * 256 + threadIdx.x;
    if (i < 192 * HD) {
        int g = i >> 6, k = i & 63;
        g_WhhT[k * 192 + g] = Whh[i];
    }
    if (blockIdx.x == 0 && threadIdx.x < HD) g_colsum[threadIdx.x] = 0.f;
}

// ---------------- K1: GRU over T=20 steps, 8 nodes / 64-thread block ----------------
__global__ void gru_kernel(const float* __restrict__ x, const float* __restrict__ Wih,
                           const float* __restrict__ bih, const float* __restrict__ bhh) {
    __shared__ float shh[NB1 * HD];
    __shared__ float shx[NB1 * IND];
    int j = threadIdx.x;                 // gate/hidden index 0..63
    int node0 = blockIdx.x * NB1;

    float wr[IND], wz[IND], wn[IND];
#pragma unroll
    for (int c = 0; c < IND; c++) {
        wr[c] = Wih[j * IND + c];
        wz[c] = Wih[(64 + j) * IND + c];
        wn[c] = Wih[(128 + j) * IND + c];
    }
    float br  = bih[j] + bhh[j];
    float bz  = bih[64 + j] + bhh[64 + j];
    float bin = bih[128 + j];
    float bhn = bhh[128 + j];

#pragma unroll
    for (int b = 0; b < NB1; b++) shh[b * HD + j] = 0.f;

    float hnew[NB1];
#pragma unroll
    for (int b = 0; b < NB1; b++) hnew[b] = 0.f;

    for (int t = 0; t < TT; t++) {
        if (j < NB1 * IND) {
            int b = j / IND, c = j % IND;
            int n = node0 + b;
            shx[b * IND + c] = (n < NN) ? x[(n * TT + t) * IND + c] : 0.f;
        }
        __syncthreads();   // shx ready; prev-step shh writes visible

        float ar[NB1], az[NB1], agn[NB1], ghn[NB1];
#pragma unroll
        for (int b = 0; b < NB1; b++) {
            float a0 = br, a1 = bz, a2 = bin;
#pragma unroll
            for (int c = 0; c < IND; c++) {
                float xv = shx[b * IND + c];
                a0 += wr[c] * xv; a1 += wz[c] * xv; a2 += wn[c] * xv;
            }
            ar[b] = a0; az[b] = a1; agn[b] = a2; ghn[b] = bhn;
        }
        const float* wt = g_WhhT;
#pragma unroll 4
        for (int k = 0; k < HD; k++) {
            float w0 = wt[k * 192 + j];
            float w1 = wt[k * 192 + 64 + j];
            float w2 = wt[k * 192 + 128 + j];
#pragma unroll
            for (int b = 0; b < NB1; b++) {
                float hk = shh[b * HD + k];
                ar[b] += w0 * hk; az[b] += w1 * hk; ghn[b] += w2 * hk;
            }
        }
        __syncthreads();   // all reads of shh done before overwrite
#pragma unroll
        for (int b = 0; b < NB1; b++) {
            float r  = sigm(ar[b]);
            float z  = sigm(az[b]);
            float nv = tanhfast(agn[b] + r * ghn[b]);
            float hv = (1.f - z) * nv + z * hnew[b];
            hnew[b] = hv;
            shh[b * HD + j] = hv;
        }
    }
#pragma unroll
    for (int b = 0; b < NB1; b++) {
        int n = node0 + b;
        if (n < NN) g_support[n * HD + j] = hnew[b];
    }
}

// ---------------- K2: head projections + f1/f2 (grid: [N/8, 2]) ----------------
__global__ void feat_kernel(const float* __restrict__ Wp, const float* __restrict__ Wn,
                            const float* __restrict__ Wup, const float* __restrict__ Wvp,
                            const float* __restrict__ Wun, const float* __restrict__ Wvn) {
    int g = blockIdx.y;
    const float* W  = g ? Wn  : Wp;
    const float* Wu = g ? Wun : Wup;
    const float* Wv = g ? Wvn : Wvp;
    int c = threadIdx.x;   // 64
    __shared__ float shW[HD * HD];
    __shared__ float sup[8 * HD];
    for (int i = c; i < HD * HD; i += 64) shW[i] = W[i];
    int n0 = blockIdx.x * 8;
#pragma unroll
    for (int b = 0; b < 8; b++) sup[b * HD + c] = g_support[(n0 + b) * HD + c];
    __syncthreads();
    int h = c >> 3, f = c & 7;
    float wu = Wu[h * 8 + f], wv = Wv[h * 8 + f];
    for (int b = 0; b < 8; b++) {
        float acc = 0.f;
#pragma unroll 8
        for (int k = 0; k < HD; k++) acc += sup[b * HD + k] * shW[k * HD + c];
        int n = n0 + b;
        g_s[g][n * HD + c] = acc;
        float t1 = acc * wu, t2 = acc * wv;
#pragma unroll
        for (int o = 4; o; o >>= 1) {
            t1 += __shfl_xor_sync(0xffffffffu, t1, o);
            t2 += __shfl_xor_sync(0xffffffffu, t2, o);
        }
        if (f == 0) {
            g_f1[g][h * NN + n] = t1;
            g_f2[g][h * NN + n] = t2;
        }
    }
}

// ---------------- K3: sparse masked attention (grid: [N, 2], 256 thr) ----------------
__global__ void attn_kernel(const float* __restrict__ adj0, const float* __restrict__ adj1) {
    int i = blockIdx.x, g = blockIdx.y;
    const float* row = (g ? adj1 : adj0) + (size_t)i * NN;
    __shared__ int cnt;
    __shared__ int idx[MAXNZ];
    int tid = threadIdx.x;
    if (tid == 0) cnt = 0;
    __syncthreads();
    const float4* row4 = (const float4*)row;   // N=3000 divisible by 4, base 16B-aligned
    for (int q = tid; q < NN / 4; q += 256) {
        float4 v = row4[q];
        if (v.x != 0.f) { int p = atomicAdd(&cnt, 1); if (p < MAXNZ) idx[p] = 4 * q;     }
        if (v.y != 0.f) { int p = atomicAdd(&cnt, 1); if (p < MAXNZ) idx[p] = 4 * q + 1; }
        if (v.z != 0.f) { int p = atomicAdd(&cnt, 1); if (p < MAXNZ) idx[p] = 4 * q + 2; }
        if (v.w != 0.f) { int p = atomicAdd(&cnt, 1); if (p < MAXNZ) idx[p] = 4 * q + 3; }
    }
    __syncthreads();
    int m = min(cnt, MAXNZ);
    int h = tid >> 5, lane = tid & 31;        // warp = head
    const float* f1h = g_f1[g] + h * NN;
    float f2v = g_f2[g][h * NN + i];
    const float* sb = g_s[g];

    // pass 1: exact row max over nonzeros
    float mx = -1e30f;
    for (int k = lane; k < m; k += 32) {
        float v = f1h[idx[k]] + f2v;
        v = v >= 0.f ? v : 0.2f * v;
        mx = fmaxf(mx, v);
    }
#pragma unroll
    for (int o = 16; o; o >>= 1) mx = fmaxf(mx, __shfl_xor_sync(0xffffffffu, mx, o));

    // pass 2: exp-sum + weighted gather
    float se = 0.f;
    float acc[8] = {0, 0, 0, 0, 0, 0, 0, 0};
    for (int k = lane; k < m; k += 32) {
        int j = idx[k];
        float v = f1h[j] + f2v;
        v = v >= 0.f ? v : 0.2f * v;
        float e = __expf(v - mx);
        se += e;
        const float4* sp = (const float4*)(sb + j * HD + h * 8);
        float4 a = sp[0], bb = sp[1];
        acc[0] += e * a.x;  acc[1] += e * a.y;  acc[2] += e * a.z;  acc[3] += e * a.w;
        acc[4] += e * bb.x; acc[5] += e * bb.y; acc[6] += e * bb.z; acc[7] += e * bb.w;
    }
#pragma unroll
    for (int o = 16; o; o >>= 1) {
        se += __shfl_xor_sync(0xffffffffu, se, o);
#pragma unroll
        for (int f = 0; f < 8; f++) acc[f] += __shfl_xor_sync(0xffffffffu, acc[f], o);
    }
    if (lane == 0) {
        float inv = se > 0.f ? 1.0f / se : 0.f;   // empty row -> zeros (matches ref mask)
        float* o2 = g_att[g] + i * HD + h * 8;
#pragma unroll
        for (int f = 0; f < 8; f++) o2[f] = acc[f] * inv;
    }
}

// ---------------- K4: residual/proj + MLPs + semantic attention (grid: N/8, 64 thr) ----------------
__global__ void comb_kernel(const float* __restrict__ pos_b, const float* __restrict__ pWp, const float* __restrict__ pbp,
                            const float* __restrict__ neg_b, const float* __restrict__ pWn, const float* __restrict__ pbn,
                            const float* __restrict__ selfW, const float* __restrict__ selfb,
                            const float* __restrict__ mpW, const float* __restrict__ mpb,
                            const float* __restrict__ mnW, const float* __restrict__ mnb,
                            const float* __restrict__ semW1, const float* __restrict__ semb1,
                            const float* __restrict__ semW2) {
    int c = threadIdx.x;   // 64
    __shared__ float sup[HD], ps[HD], ns[HD], e0[HD], e1[HD], e2[HD];
    __shared__ float red[2][3];
    int n0 = blockIdx.x * 8;
    int warp = c >> 5, lane = c & 31;
    float colpart = 0.f;
    for (int b = 0; b < 8; b++) {
        int n = n0 + b;
        sup[c] = g_support[n * HD + c];
        __syncthreads();
        float ap = g_att[0][n * HD + c] + pos_b[c] + pbp[c];
        float an = g_att[1][n * HD + c] + neg_b[c] + pbn[c];
        float sv = selfb[c];
        for (int k = 0; k < HD; k++) {
            float s = sup[k];
            ap += s * pWp[k * HD + c];
            an += s * pWn[k * HD + c];
            sv += s * selfW[k * HD + c];
        }
        ps[c] = ap; ns[c] = an;
        __syncthreads();
        float spv = mpb[c], snv = mnb[c];
        for (int k = 0; k < HD; k++) {
            spv += ps[k] * mpW[k * HD + c];
            snv += ns[k] * mnW[k * HD + c];
        }
        e0[c] = sv; e1[c] = spv; e2[c] = snv;
        __syncthreads();
        float t0 = semb1[c], t1 = semb1[c], t2 = semb1[c];
        for (int k = 0; k < HD; k++) {
            float w = semW1[k * HD + c];
            t0 += e0[k] * w; t1 += e1[k] * w; t2 += e2[k] * w;
        }
        float w2v = semW2[c];
        t0 = tanhfast(t0) * w2v;
        t1 = tanhfast(t1) * w2v;
        t2 = tanhfast(t2) * w2v;
#pragma unroll
        for (int o = 16; o; o >>= 1) {
            t0 += __shfl_xor_sync(0xffffffffu, t0, o);
            t1 += __shfl_xor_sync(0xffffffffu, t1, o);
            t2 += __shfl_xor_sync(0xffffffffu, t2, o);
        }
        if (lane == 0) { red[warp][0] = t0; red[warp][1] = t1; red[warp][2] = t2; }
        __syncthreads();
        float w0  = red[0][0] + red[1][0];
        float w1  = red[0][1] + red[1][1];
        float ww2 = red[0][2] + red[1][2];
        float mw = fmaxf(w0, fmaxf(w1, ww2));
        float b0 = __expf(w0 - mw), b1 = __expf(w1 - mw), b2 = __expf(ww2 - mw);
        float inv = 1.f / (b0 + b1 + b2);
        float emb = (b0 * sv + b1 * spv + b2 * snv) * inv;
        g_emb[n * HD + c] = emb;
        colpart += emb;
    }
    atomicAdd(&g_colsum[c], colpart);
}

// ---------------- K5: pairnorm + prediction head (warp per node) ----------------
__global__ void final_kernel(const float* __restrict__ predW, const float* __restrict__ predb,
                             float* __restrict__ out) {
    int warp = threadIdx.x >> 5, lane = threadIdx.x & 31;
    int n = blockIdx.x * 4 + warp;
    float invn = 1.0f / NN;
    float x0 = g_emb[n * HD + lane]      - g_colsum[lane]      * invn;
    float x1 = g_emb[n * HD + 32 + lane] - g_colsum[32 + lane] * invn;
    float ss = x0 * x0 + x1 * x1;
    float dt = x0 * predW[lane] + x1 * predW[32 + lane];
#pragma unroll
    for (int o = 16; o; o >>= 1) {
        ss += __shfl_xor_sync(0xffffffffu, ss, o);
        dt += __shfl_xor_sync(0xffffffffu, dt, o);
    }
    if (lane == 0) out[n] = sigm(dt * rsqrtf(1e-6f + ss) + predb[0]);
}

// ---------------- launch ----------------
extern "C" void kernel_launch(void* const* d_in, const int* in_sizes, int n_in,
                              void* d_out, int out_size) {
    (void)in_sizes; (void)n_in; (void)out_size;
    const float* inputs   = (const float*)d_in[0];
    const float* pos_adj  = (const float*)d_in[1];
    const float* neg_adj  = (const float*)d_in[2];
    const float* Wih      = (const float*)d_in[3];
    const float* Whh      = (const float*)d_in[4];
    const float* bih      = (const float*)d_in[5];
    const float* bhh      = (const float*)d_in[6];
    const float* pos_W    = (const float*)d_in[7];
    const float* pos_Wu   = (const float*)d_in[8];
    const float* pos_Wv   = (const float*)d_in[9];
    const float* pos_b    = (const float*)d_in[10];
    const float* pos_projW= (const float*)d_in[11];
    const float* pos_projb= (const float*)d_in[12];
    const float* neg_W    = (const float*)d_in[13];
    const float* neg_Wu   = (const float*)d_in[14];
    const float* neg_Wv   = (const float*)d_in[15];
    const float* neg_b    = (const float*)d_in[16];
    const float* neg_projW= (const float*)d_in[17];
    const float* neg_projb= (const float*)d_in[18];
    const float* self_W   = (const float*)d_in[19];
    const float* self_b   = (const float*)d_in[20];
    const float* mlpp_W   = (const float*)d_in[21];
    const float* mlpp_b   = (const float*)d_in[22];
    const float* mlpn_W   = (const float*)d_in[23];
    const float* mlpn_b   = (const float*)d_in[24];
    const float* sem_W1   = (const float*)d_in[25];
    const float* sem_b1   = (const float*)d_in[26];
    const float* sem_W2   = (const float*)d_in[27];
    const float* pred_W   = (const float*)d_in[28];
    const float* pred_b   = (const float*)d_in[29];

    prep_kernel<<<48, 256>>>(Whh);
    gru_kernel<<<(NN + NB1 - 1) / NB1, 64>>>(inputs, Wih, bih, bhh);
    feat_kernel<<<dim3(NN / 8, 2), 64>>>(pos_W, neg_W, pos_Wu, pos_Wv, neg_Wu, neg_Wv);
    attn_kernel<<<dim3(NN, 2), 256>>>(pos_adj, neg_adj);
    comb_kernel<<<NN / 8, 64>>>(pos_b, pos_projW, pos_projb, neg_b, neg_projW, neg_projb,
                                self_W, self_b, mlpp_W, mlpp_b, mlpn_W, mlpn_b,
                                sem_W1, sem_b1, sem_W2);
    final_kernel<<<NN / 4, 128>>>(pred_W, pred_b, (float*)d_out);
}

// round 2
// speedup vs baseline: 1.0460x; 1.0460x over previous
#include <cuda_runtime.h>

#define NN 3000
#define TT 20
#define IND 6
#define HD 64
#define NH 8
#define NB1 4
#define MAXNZ 512

// ---------------- scratch (no allocation allowed) ----------------
__device__ float2 g_Whh2[HD * 192];         // recurrent weights, duplicated pairs [k][r]
__device__ float g_support[NN * HD];        // GRU final hidden
__device__ float g_s[2][NN * HD];           // per-graph head features  [n][h*8+f]
__device__ float g_f1[2][NH * NN];          // source scores  [g][h*N+n]
__device__ float g_f2[2][NH * NN];          // dest scores    [g][h*N+n]
__device__ float g_f1max[16];               // global per-(g,h) max of f1
__device__ float g_att[2][NN * HD];         // attention outputs
__device__ float g_emb[NN * HD];            // pre-pairnorm embedding
__device__ float g_colsum[HD];              // column sums for pairnorm mean

__device__ __forceinline__ float sigm(float x) { return 1.0f / (1.0f + __expf(-x)); }
__device__ __forceinline__ float tanhfast(float x) { return 2.0f * sigm(2.0f * x) - 1.0f; }

// packed f32x2 helpers
__device__ __forceinline__ unsigned long long pk(float lo, float hi) {
    unsigned long long r;
    asm("mov.b64 %0, {%1,%2};" : "=l"(r) : "f"(lo), "f"(hi));
    return r;
}
__device__ __forceinline__ void upk(unsigned long long v, float& lo, float& hi) {
    asm("mov.b64 {%0,%1}, %2;" : "=f"(lo), "=f"(hi) : "l"(v));
}
__device__ __forceinline__ void ffma2(unsigned long long& d, unsigned long long a, unsigned long long b) {
    asm("fma.rn.f32x2 %0, %1, %2, %0;" : "+l"(d) : "l"(a), "l"(b));
}

// ---------------- K0: duplicate Whh pairs + zero colsum ----------------
__global__ void prep_kernel(const float* __restrict__ Whh) {
    int i = blockIdx.x * 256 + threadIdx.x;
    if (i < 192 * HD) {
        int r = i >> 6, k = i & 63;
        float w = Whh[i];
        g_Whh2[k * 192 + r] = make_float2(w, w);
    }
    if (blockIdx.x == 0 && threadIdx.x < HD) g_colsum[threadIdx.x] = 0.f;
}

// ---------------- K1: GRU, 4 nodes / 64-thread block, packed f32x2 ----------------
__global__ void gru_kernel(const float* __restrict__ x, const float* __restrict__ Wih,
                           const float* __restrict__ bih, const float* __restrict__ bhh) {
    __shared__ float4 shh4[HD];    // [k] -> 4 nodes hidden
    __shared__ float4 shx4[IND];   // [c] -> 4 nodes input
    float* shxf = (float*)shx4;
    int j = threadIdx.x;           // gate/hidden index 0..63
    int node0 = blockIdx.x * NB1;  // NN divisible by 4

    float wr[IND], wz[IND], wn[IND];
#pragma unroll
    for (int c = 0; c < IND; c++) {
        wr[c] = Wih[j * IND + c];
        wz[c] = Wih[(64 + j) * IND + c];
        wn[c] = Wih[(128 + j) * IND + c];
    }
    float br  = bih[j] + bhh[j];
    float bz  = bih[64 + j] + bhh[64 + j];
    float bin = bih[128 + j];
    float bhn = bhh[128 + j];
    unsigned long long pbr = pk(br, br), pbz = pk(bz, bz);
    unsigned long long pbi = pk(bin, bin), pbh = pk(bhn, bhn);

    shh4[j] = make_float4(0.f, 0.f, 0.f, 0.f);
    float h0 = 0.f, h1 = 0.f, h2 = 0.f, h3 = 0.f;

    const unsigned long long* w2 = (const unsigned long long*)g_Whh2;

    for (int t = 0; t < TT; t++) {
        if (j < NB1 * IND) {
            int c = j >> 2, b = j & 3;
            shxf[c * 4 + b] = x[((node0 + b) * TT + t) * IND + c];
        }
        __syncthreads();   // shx ready; prev shh writes visible

        unsigned long long ar01 = pbr, ar23 = pbr;
        unsigned long long az01 = pbz, az23 = pbz;
        unsigned long long an01 = pbi, an23 = pbi;
        unsigned long long gn01 = pbh, gn23 = pbh;

#pragma unroll
        for (int c = 0; c < IND; c++) {
            float4 xv = shx4[c];
            unsigned long long x01 = pk(xv.x, xv.y), x23 = pk(xv.z, xv.w);
            unsigned long long pwr = pk(wr[c], wr[c]);
            unsigned long long pwz = pk(wz[c], wz[c]);
            unsigned long long pwn = pk(wn[c], wn[c]);
            ffma2(ar01, pwr, x01); ffma2(ar23, pwr, x23);
            ffma2(az01, pwz, x01); ffma2(az23, pwz, x23);
            ffma2(an01, pwn, x01); ffma2(an23, pwn, x23);
        }

#pragma unroll 4
        for (int k = 0; k < HD; k++) {
            float4 hv = shh4[k];
            unsigned long long h01 = pk(hv.x, hv.y), h23 = pk(hv.z, hv.w);
            unsigned long long w0 = w2[k * 192 + j];
            unsigned long long w1 = w2[k * 192 + 64 + j];
            unsigned long long wn2 = w2[k * 192 + 128 + j];
            ffma2(ar01, w0, h01);  ffma2(ar23, w0, h23);
            ffma2(az01, w1, h01);  ffma2(az23, w1, h23);
            ffma2(gn01, wn2, h01); ffma2(gn23, wn2, h23);
        }
        __syncthreads();   // all reads of shh done before overwrite

        float a0, a1, a2, a3, z0, z1, z2, z3, n0, n1, n2, n3, g0, g1, g2, g3;
        upk(ar01, a0, a1); upk(ar23, a2, a3);
        upk(az01, z0, z1); upk(az23, z2, z3);
        upk(an01, n0, n1); upk(an23, n2, n3);
        upk(gn01, g0, g1); upk(gn23, g2, g3);

        float r0 = sigm(a0), r1 = sigm(a1), r2 = sigm(a2), r3 = sigm(a3);
        float zz0 = sigm(z0), zz1 = sigm(z1), zz2 = sigm(z2), zz3 = sigm(z3);
        float nv0 = tanhfast(n0 + r0 * g0);
        float nv1 = tanhfast(n1 + r1 * g1);
        float nv2 = tanhfast(n2 + r2 * g2);
        float nv3 = tanhfast(n3 + r3 * g3);
        h0 = (1.f - zz0) * nv0 + zz0 * h0;
        h1 = (1.f - zz1) * nv1 + zz1 * h1;
        h2 = (1.f - zz2) * nv2 + zz2 * h2;
        h3 = (1.f - zz3) * nv3 + zz3 * h3;
        shh4[j] = make_float4(h0, h1, h2, h3);
    }
    g_support[(node0 + 0) * HD + j] = h0;
    g_support[(node0 + 1) * HD + j] = h1;
    g_support[(node0 + 2) * HD + j] = h2;
    g_support[(node0 + 3) * HD + j] = h3;
}

// ---------------- K2: head projections + f1/f2 (grid: [N/8, 2]) ----------------
__global__ void feat_kernel(const float* __restrict__ Wp, const float* __restrict__ Wn,
                            const float* __restrict__ Wup, const float* __restrict__ Wvp,
                            const float* __restrict__ Wun, const float* __restrict__ Wvn) {
    int g = blockIdx.y;
    const float* W  = g ? Wn  : Wp;
    const float* Wu = g ? Wun : Wup;
    const float* Wv = g ? Wvn : Wvp;
    int c = threadIdx.x;   // 64
    __shared__ float shW[HD * HD];
    __shared__ float sup[8 * HD];
    for (int i = c; i < HD * HD; i += 64) shW[i] = W[i];
    int n0 = blockIdx.x * 8;
#pragma unroll
    for (int b = 0; b < 8; b++) sup[b * HD + c] = g_support[(n0 + b) * HD + c];
    __syncthreads();
    int h = c >> 3, f = c & 7;
    float wu = Wu[h * 8 + f], wv = Wv[h * 8 + f];
    for (int b = 0; b < 8; b++) {
        float acc = 0.f;
#pragma unroll 8
        for (int k = 0; k < HD; k++) acc += sup[b * HD + k] * shW[k * HD + c];
        int n = n0 + b;
        g_s[g][n * HD + c] = acc;
        float t1 = acc * wu, t2 = acc * wv;
#pragma unroll
        for (int o = 4; o; o >>= 1) {
            t1 += __shfl_xor_sync(0xffffffffu, t1, o);
            t2 += __shfl_xor_sync(0xffffffffu, t2, o);
        }
        if (f == 0) {
            g_f1[g][h * NN + n] = t1;
            g_f2[g][h * NN + n] = t2;
        }
    }
}

// ---------------- K2b: global per-(g,h) max of f1 (16 blocks) ----------------
__global__ void fmax_kernel() {
    int b = blockIdx.x;                 // g*8 + h
    int g = b >> 3, h = b & 7;
    const float* p = g_f1[g] + h * NN;
    __shared__ float red[4];
    float mx = -1e30f;
    for (int n = threadIdx.x; n < NN; n += 128) mx = fmaxf(mx, p[n]);
#pragma unroll
    for (int o = 16; o; o >>= 1) mx = fmaxf(mx, __shfl_xor_sync(0xffffffffu, mx, o));
    if ((threadIdx.x & 31) == 0) red[threadIdx.x >> 5] = mx;
    __syncthreads();
    if (threadIdx.x == 0)
        g_f1max[b] = fmaxf(fmaxf(red[0], red[1]), fmaxf(red[2], red[3]));
}

// ---------------- K3: sparse masked attention, single pass (grid: [N, 2]) ----------------
__global__ void attn_kernel(const float* __restrict__ adj0, const float* __restrict__ adj1) {
    int i = blockIdx.x, g = blockIdx.y;
    const float* row = (g ? adj1 : adj0) + (size_t)i * NN;
    __shared__ int cnt;
    __shared__ int idx[MAXNZ];
    int tid = threadIdx.x, lane = tid & 31;
    if (tid == 0) cnt = 0;
    __syncthreads();

    // ballot-compacted nonzero scan (N=3000 -> 750 float4 chunks, 3 strided iters)
    const float4* row4 = (const float4*)row;
#pragma unroll
    for (int it = 0; it < 3; it++) {
        int q = it * 256 + tid;
        float4 v = make_float4(0.f, 0.f, 0.f, 0.f);
        if (q < NN / 4) v = row4[q];
#pragma unroll
        for (int c = 0; c < 4; c++) {
            float val = (c == 0) ? v.x : (c == 1) ? v.y : (c == 2) ? v.z : v.w;
            unsigned bal = __ballot_sync(0xffffffffu, val != 0.f);
            if (bal) {
                int leader = __ffs(bal) - 1;
                int base;
                if (lane == leader) base = atomicAdd(&cnt, __popc(bal));
                base = __shfl_sync(0xffffffffu, base, leader);
                if (val != 0.f) {
                    int p = base + __popc(bal & ((1u << lane) - 1u));
                    if (p < MAXNZ) idx[p] = 4 * q + c;
                }
            }
        }
    }
    __syncthreads();
    int m = min(cnt, MAXNZ);

    int h = tid >> 5;                         // warp = head
    const float* f1h = g_f1[g] + h * NN;
    float f2v = g_f2[g][h * NN + i];
    // shift M >= max over row nonzeros (leaky monotone; softmax shift-invariant)
    float Mv = g_f1max[g * 8 + h] + f2v;
    Mv = Mv >= 0.f ? Mv : 0.2f * Mv;
    const float* sb = g_s[g];

    float se = 0.f;
    float acc[8] = {0, 0, 0, 0, 0, 0, 0, 0};
    for (int k = lane; k < m; k += 32) {
        int j = idx[k];
        float v = f1h[j] + f2v;
        v = v >= 0.f ? v : 0.2f * v;
        float e = __expf(v - Mv);
        se += e;
        const float4* sp = (const float4*)(sb + j * HD + h * 8);
        float4 a = sp[0], bb = sp[1];
        acc[0] += e * a.x;  acc[1] += e * a.y;  acc[2] += e * a.z;  acc[3] += e * a.w;
        acc[4] += e * bb.x; acc[5] += e * bb.y; acc[6] += e * bb.z; acc[7] += e * bb.w;
    }
#pragma unroll
    for (int o = 16; o; o >>= 1) {
        se += __shfl_xor_sync(0xffffffffu, se, o);
#pragma unroll
        for (int f = 0; f < 8; f++) acc[f] += __shfl_xor_sync(0xffffffffu, acc[f], o);
    }
    if (lane == 0) {
        float inv = se > 0.f ? 1.0f / se : 0.f;   // empty row -> zeros (matches ref mask)
        float* o2 = g_att[g] + i * HD + h * 8;
#pragma unroll
        for (int f = 0; f < 8; f++) o2[f] = acc[f] * inv;
    }
}

// ---------------- K4: residual/proj + MLPs + semantic attention (grid: N/8) ----------------
__global__ void comb_kernel(const float* __restrict__ pos_b, const float* __restrict__ pWp, const float* __restrict__ pbp,
                            const float* __restrict__ neg_b, const float* __restrict__ pWn, const float* __restrict__ pbn,
                            const float* __restrict__ selfW, const float* __restrict__ selfb,
                            const float* __restrict__ mpW, const float* __restrict__ mpb,
                            const float* __restrict__ mnW, const float* __restrict__ mnb,
                            const float* __restrict__ semW1, const float* __restrict__ semb1,
                            const float* __restrict__ semW2) {
    int c = threadIdx.x;   // 64
    __shared__ float sup[HD], ps[HD], ns[HD], e0[HD], e1[HD], e2[HD];
    __shared__ float red[2][3];
    int n0 = blockIdx.x * 8;
    int warp = c >> 5, lane = c & 31;
    float colpart = 0.f;
    for (int b = 0; b < 8; b++) {
        int n = n0 + b;
        sup[c] = g_support[n * HD + c];
        __syncthreads();
        float ap = g_att[0][n * HD + c] + pos_b[c] + pbp[c];
        float an = g_att[1][n * HD + c] + neg_b[c] + pbn[c];
        float sv = selfb[c];
        for (int k = 0; k < HD; k++) {
            float s = sup[k];
            ap += s * pWp[k * HD + c];
            an += s * pWn[k * HD + c];
            sv += s * selfW[k * HD + c];
        }
        ps[c] = ap; ns[c] = an;
        __syncthreads();
        float spv = mpb[c], snv = mnb[c];
        for (int k = 0; k < HD; k++) {
            spv += ps[k] * mpW[k * HD + c];
            snv += ns[k] * mnW[k * HD + c];
        }
        e0[c] = sv; e1[c] = spv; e2[c] = snv;
        __syncthreads();
        float t0 = semb1[c], t1 = semb1[c], t2 = semb1[c];
        for (int k = 0; k < HD; k++) {
            float w = semW1[k * HD + c];
            t0 += e0[k] * w; t1 += e1[k] * w; t2 += e2[k] * w;
        }
        float w2v = semW2[c];
        t0 = tanhfast(t0) * w2v;
        t1 = tanhfast(t1) * w2v;
        t2 = tanhfast(t2) * w2v;
#pragma unroll
        for (int o = 16; o; o >>= 1) {
            t0 += __shfl_xor_sync(0xffffffffu, t0, o);
            t1 += __shfl_xor_sync(0xffffffffu, t1, o);
            t2 += __shfl_xor_sync(0xffffffffu, t2, o);
        }
        if (lane == 0) { red[warp][0] = t0; red[warp][1] = t1; red[warp][2] = t2; }
        __syncthreads();
        float w0  = red[0][0] + red[1][0];
        float w1  = red[0][1] + red[1][1];
        float ww2 = red[0][2] + red[1][2];
        float mw = fmaxf(w0, fmaxf(w1, ww2));
        float b0 = __expf(w0 - mw), b1 = __expf(w1 - mw), b2 = __expf(ww2 - mw);
        float inv = 1.f / (b0 + b1 + b2);
        float emb = (b0 * sv + b1 * spv + b2 * snv) * inv;
        g_emb[n * HD + c] = emb;
        colpart += emb;
    }
    atomicAdd(&g_colsum[c], colpart);
}

// ---------------- K5: pairnorm + prediction head (warp per node) ----------------
__global__ void final_kernel(const float* __restrict__ predW, const float* __restrict__ predb,
                             float* __restrict__ out) {
    int warp = threadIdx.x >> 5, lane = threadIdx.x & 31;
    int n = blockIdx.x * 4 + warp;
    float invn = 1.0f / NN;
    float x0 = g_emb[n * HD + lane]      - g_colsum[lane]      * invn;
    float x1 = g_emb[n * HD + 32 + lane] - g_colsum[32 + lane] * invn;
    float ss = x0 * x0 + x1 * x1;
    float dt = x0 * predW[lane] + x1 * predW[32 + lane];
#pragma unroll
    for (int o = 16; o; o >>= 1) {
        ss += __shfl_xor_sync(0xffffffffu, ss, o);
        dt += __shfl_xor_sync(0xffffffffu, dt, o);
    }
    if (lane == 0) out[n] = sigm(dt * rsqrtf(1e-6f + ss) + predb[0]);
}

// ---------------- launch ----------------
extern "C" void kernel_launch(void* const* d_in, const int* in_sizes, int n_in,
                              void* d_out, int out_size) {
    (void)in_sizes; (void)n_in; (void)out_size;
    const float* inputs   = (const float*)d_in[0];
    const float* pos_adj  = (const float*)d_in[1];
    const float* neg_adj  = (const float*)d_in[2];
    const float* Wih      = (const float*)d_in[3];
    const float* Whh      = (const float*)d_in[4];
    const float* bih      = (const float*)d_in[5];
    const float* bhh      = (const float*)d_in[6];
    const float* pos_W    = (const float*)d_in[7];
    const float* pos_Wu   = (const float*)d_in[8];
    const float* pos_Wv   = (const float*)d_in[9];
    const float* pos_b    = (const float*)d_in[10];
    const float* pos_projW= (const float*)d_in[11];
    const float* pos_projb= (const float*)d_in[12];
    const float* neg_W    = (const float*)d_in[13];
    const float* neg_Wu   = (const float*)d_in[14];
    const float* neg_Wv   = (const float*)d_in[15];
    const float* neg_b    = (const float*)d_in[16];
    const float* neg_projW= (const float*)d_in[17];
    const float* neg_projb= (const float*)d_in[18];
    const float* self_W   = (const float*)d_in[19];
    const float* self_b   = (const float*)d_in[20];
    const float* mlpp_W   = (const float*)d_in[21];
    const float* mlpp_b   = (const float*)d_in[22];
    const float* mlpn_W   = (const float*)d_in[23];
    const float* mlpn_b   = (const float*)d_in[24];
    const float* sem_W1   = (const float*)d_in[25];
    const float* sem_b1   = (const float*)d_in[26];
    const float* sem_W2   = (const float*)d_in[27];
    const float* pred_W   = (const float*)d_in[28];
    const float* pred_b   = (const float*)d_in[29];

    prep_kernel<<<48, 256>>>(Whh);
    gru_kernel<<<NN / NB1, 64>>>(inputs, Wih, bih, bhh);
    feat_kernel<<<dim3(NN / 8, 2), 64>>>(pos_W, neg_W, pos_Wu, pos_Wv, neg_Wu, neg_Wv);
    fmax_kernel<<<16, 128>>>();
    attn_kernel<<<dim3(NN, 2), 256>>>(pos_adj, neg_adj);
    comb_kernel<<<NN / 8, 64>>>(pos_b, pos_projW, pos_projb, neg_b, neg_projW, neg_projb,
                                self_W, self_b, mlpp_W, mlpp_b, mlpn_W, mlpn_b,
                                sem_W1, sem_b1, sem_W2);
    final_kernel<<<NN / 4, 128>>>(pred_W, pred_b, (float*)d_out);
}